// round 1
// baseline (speedup 1.0000x reference)
#include <cuda_runtime.h>
#include <stdint.h>

#define DATA_DIM 4096
#define PAIRS    (DATA_DIM / 2)   // 2048
#define QUADS    (DATA_DIM / 4)   // 1024 float4 per row
#define BATCH    16384

// Scratch: pair-level permutation map (no device allocation allowed).
__device__ int g_pairmap[PAIRS];

// Build pairmap[j] = perm_idx[2*j] / 2, auto-detecting int32 vs int64 index dtype.
// perm_idx[2j+1] is always an odd (nonzero) value, so for an int32 payload the
// 32-bit word at offset 1 is nonzero; for little-endian int64 it is the high
// word of perm_idx[0] and is zero (all indices < 2^31).
__global__ void build_pairmap_kernel(const void* __restrict__ perm) {
    const int* p32 = (const int*)perm;
    bool is64 = (p32[1] == 0) && (p32[3] == 0) && (p32[5] == 0) && (p32[7] == 0);
    int j = blockIdx.x * blockDim.x + threadIdx.x;
    if (j < PAIRS) {
        int v;
        if (is64) {
            v = (int)((const long long*)perm)[2 * j];
        } else {
            v = p32[2 * j];
        }
        g_pairmap[j] = v >> 1;   // source pair index
    }
}

__global__ void __launch_bounds__(256)
permute_gather_kernel(const float* __restrict__ z, float4* __restrict__ out,
                      long long total_quads) {
    __shared__ int s_pm[PAIRS];
    for (int i = threadIdx.x; i < PAIRS; i += blockDim.x)
        s_pm[i] = g_pairmap[i];
    __syncthreads();

    const float2* __restrict__ z2 = (const float2*)z;

    long long idx = (long long)blockIdx.x * blockDim.x + threadIdx.x;
    long long stride = (long long)gridDim.x * blockDim.x;

    for (; idx < total_quads; idx += stride) {
        int q = (int)(idx & (QUADS - 1));       // quad within row
        long long row = idx >> 10;              // QUADS == 1024
        const float2* rowbase = z2 + row * (long long)PAIRS;
        int sp0 = s_pm[2 * q];
        int sp1 = s_pm[2 * q + 1];
        float2 a = __ldg(&rowbase[sp0]);
        float2 b = __ldg(&rowbase[sp1]);
        out[idx] = make_float4(a.x, a.y, b.x, b.y);
    }
}

extern "C" void kernel_launch(void* const* d_in, const int* in_sizes, int n_in,
                              void* d_out, int out_size) {
    const float* z    = (const float*)d_in[0];
    const void*  perm = d_in[1];
    float4*      out  = (float4*)d_out;

    build_pairmap_kernel<<<(PAIRS + 255) / 256, 256>>>(perm);

    long long total_quads = (long long)BATCH * QUADS;  // 16,777,216
    int threads = 256;
    int blocks = 148 * 16;  // grid-stride; ~27 iters/thread, amortizes smem fill
    permute_gather_kernel<<<blocks, threads>>>(z, out, total_quads);
}

// round 3
// speedup vs baseline: 1.3635x; 1.3635x over previous
#include <cuda_runtime.h>
#include <stdint.h>

#define DATA_DIM 4096
#define PAIRS    (DATA_DIM / 2)   // 2048
#define QUADS    (DATA_DIM / 4)   // 1024 float4 per row
#define BATCH    16384

// Scratch: pair-level permutation map (no device allocation allowed).
__device__ int g_pairmap[PAIRS];

// Build pairmap[j] = perm_idx[2*j] / 2, auto-detecting int32 vs int64 index dtype.
// perm_idx[2j+1] is always odd (nonzero), so for int32 payload word[1] != 0;
// for little-endian int64 word[1] is the high word of perm_idx[0] and is 0.
__global__ void build_pairmap_kernel(const void* __restrict__ perm) {
    const int* p32 = (const int*)perm;
    bool is64 = (p32[1] == 0) && (p32[3] == 0) && (p32[5] == 0) && (p32[7] == 0);
    int j = blockIdx.x * blockDim.x + threadIdx.x;
    if (j < PAIRS) {
        int v;
        if (is64) {
            v = (int)((const long long*)perm)[2 * j];
        } else {
            v = p32[2 * j];
        }
        g_pairmap[j] = v >> 1;   // source pair index
    }
}

// One CTA per row. Coalesced gmem load -> deinterleaved smem -> random LDS
// gather -> coalesced float4 store. All DRAM traffic is fully coalesced.
__global__ void __launch_bounds__(256)
permute_rows_kernel(const float* __restrict__ z, float4* __restrict__ out) {
    __shared__ float s_ev[PAIRS];   // even elements z[2*sp]
    __shared__ float s_od[PAIRS];   // odd  elements z[2*sp+1]
    __shared__ int2  s_pm[QUADS];   // (pm[2q], pm[2q+1]) per output quad

    const int tid = threadIdx.x;
    const long long row = blockIdx.x;

    const float4* __restrict__ zr = (const float4*)(z + row * DATA_DIM);
    float2* sev2 = (float2*)s_ev;
    float2* sod2 = (float2*)s_od;
    const int2* __restrict__ pm2 = (const int2*)g_pairmap;

    // Load pair-map (coalesced LDG.64 -> STS.64, conflict-free).
    #pragma unroll
    for (int i = tid; i < QUADS; i += 256)
        s_pm[i] = pm2[i];

    // Load row (coalesced LDG.128), deinterleave into even/odd float arrays.
    // float4 i holds pairs 2i and 2i+1: (ev[2i], od[2i], ev[2i+1], od[2i+1]).
    // STS.64 to float2 index i -> banks {2i,2i+1}: conflict-free per phase.
    #pragma unroll
    for (int i = tid; i < QUADS; i += 256) {
        float4 v = __ldg(&zr[i]);
        sev2[i] = make_float2(v.x, v.z);
        sod2[i] = make_float2(v.y, v.w);
    }
    __syncthreads();

    // Gather: random 32-bit LDS across all 32 banks, coalesced STG.128.
    float4* __restrict__ outr = out + row * QUADS;
    #pragma unroll
    for (int i = tid; i < QUADS; i += 256) {
        int2 p = s_pm[i];
        outr[i] = make_float4(s_ev[p.x], s_od[p.x], s_ev[p.y], s_od[p.y]);
    }
}

extern "C" void kernel_launch(void* const* d_in, const int* in_sizes, int n_in,
                              void* d_out, int out_size) {
    const float* z    = (const float*)d_in[0];
    const void*  perm = d_in[1];
    float4*      out  = (float4*)d_out;

    build_pairmap_kernel<<<(PAIRS + 255) / 256, 256>>>(perm);
    permute_rows_kernel<<<BATCH, 256>>>(z, out);
}